// round 8
// baseline (speedup 1.0000x reference)
#include <cuda_runtime.h>
#include <cuda_bf16.h>
#include <math.h>
#include <stdint.h>

#define BATCH 1024
#define HDIM  1024
#define GATES 4096
#define INDIM 768
#define KDIM  1792
#define EPSV  1e-8f

// ---------------- scratch (no allocations allowed) ----------------
__device__ float g_h[BATCH * HDIM];
__device__ float g_c[BATCH * HDIM];
__device__ float g_t[BATCH * HDIM];
__device__ float g_biasp[GATES];
__device__ __align__(16) __nv_bfloat16 g_Ah[BATCH * KDIM];
__device__ __align__(16) __nv_bfloat16 g_Al[BATCH * KDIM];
__device__ __align__(16) __nv_bfloat16 g_Wh[(size_t)GATES * KDIM];
__device__ __align__(16) __nv_bfloat16 g_Wl[(size_t)GATES * KDIM];
__device__ __align__(16) __nv_bfloat16 g_Fh[(size_t)HDIM * HDIM];
__device__ __align__(16) __nv_bfloat16 g_Fl[(size_t)HDIM * HDIM];

// ---------------- helpers ----------------
__device__ __forceinline__ uint32_t smem_u32(const void* p) {
    uint32_t a;
    asm("{ .reg .u64 t; cvta.to.shared.u64 t, %1; cvt.u32.u64 %0, t; }" : "=r"(a) : "l"(p));
    return a;
}
static __device__ __forceinline__ void cpa16(uint32_t s, const void* g) {
    asm volatile("cp.async.cg.shared.global [%0], [%1], 16;" :: "r"(s), "l"(g));
}
static __device__ __forceinline__ void ldmx4(uint32_t* r, uint32_t addr) {
    asm volatile("ldmatrix.sync.aligned.m8n8.x4.shared.b16 {%0,%1,%2,%3}, [%4];"
                 : "=r"(r[0]), "=r"(r[1]), "=r"(r[2]), "=r"(r[3]) : "r"(addr));
}
static __device__ __forceinline__ void mma16816(float* d, const uint32_t* a, const uint32_t* b) {
    asm volatile(
        "mma.sync.aligned.m16n8k16.row.col.f32.bf16.bf16.f32 "
        "{%0,%1,%2,%3}, {%4,%5,%6,%7}, {%8,%9}, {%0,%1,%2,%3};"
        : "+f"(d[0]), "+f"(d[1]), "+f"(d[2]), "+f"(d[3])
        : "r"(a[0]), "r"(a[1]), "r"(a[2]), "r"(a[3]), "r"(b[0]), "r"(b[1]));
}
static __device__ __forceinline__ float sigm(float v) { return 1.f / (1.f + __expf(-v)); }
static __device__ __forceinline__ float tanhfast(float v) { return 2.f / (1.f + __expf(-2.f * v)) - 1.f; }

// ---------------- init ----------------
__global__ void zero_state() {
    int idx = blockIdx.x * 256 + threadIdx.x;
    g_h[idx] = 0.f;
    g_c[idx] = 0.f;
    int row = idx >> 10, j = idx & 1023;
    __nv_bfloat16 z = __float2bfloat16(0.f);
    g_Ah[(size_t)row * KDIM + 768 + j] = z;
    g_Al[(size_t)row * KDIM + 768 + j] = z;
}

// ---------------- weight convert: (unit,gate) interleave permutation + bf16 split ----------------
__global__ __launch_bounds__(256) void convert_weights(
    const float* __restrict__ W_ih, const float* __restrict__ W_hh,
    const float* __restrict__ b_ih, const float* __restrict__ b_hh)
{
    int pc = blockIdx.x;                    // permuted row: unit = pc>>2, gate = pc&3
    int orig = (pc & 3) * 1024 + (pc >> 2);
    for (int c = threadIdx.x; c < KDIM; c += 256) {
        float w = (c < 768) ? W_ih[(size_t)orig * 768 + c]
                            : W_hh[(size_t)orig * 1024 + (c - 768)];
        __nv_bfloat16 wh = __float2bfloat16(w);
        g_Wh[(size_t)pc * KDIM + c] = wh;
        g_Wl[(size_t)pc * KDIM + c] = __float2bfloat16(w - __bfloat162float(wh));
    }
    if (threadIdx.x == 0) g_biasp[pc] = b_ih[orig] + b_hh[orig];
}

__global__ __launch_bounds__(256) void convert_wfc0(const float* __restrict__ W_fc0) {
    int r = blockIdx.x;
    for (int c = threadIdx.x; c < HDIM; c += 256) {
        float w = W_fc0[(size_t)r * HDIM + c];
        __nv_bfloat16 wh = __float2bfloat16(w);
        g_Fh[(size_t)r * HDIM + c] = wh;
        g_Fl[(size_t)r * HDIM + c] = __float2bfloat16(w - __bfloat162float(wh));
    }
}

// ---------------- fused attention + filterbank + glimpse ----------------
// One block per batch element; Fx/Fy live in smem only; writes split-bf16 r into A.
__global__ __launch_bounds__(256) void att_glimpse(
    const float* __restrict__ x,
    const float* __restrict__ W_att, const float* __restrict__ b_att)
{
    int b = blockIdx.x;
    int tid = threadIdx.x;

    __shared__ float fx[16][65];
    __shared__ float fy[16][65];
    __shared__ float simg[64][64];
    __shared__ float stmp[16][64];
    __shared__ float red[8][5];
    __shared__ float p[5];
    __shared__ float rs[32];

    // ---- attention params: p = h @ W_att^T + b_att ----
    const float* hrow = g_h + (size_t)b * HDIM;
    float a0 = 0.f, a1 = 0.f, a2 = 0.f, a3 = 0.f, a4 = 0.f;
    for (int k = tid; k < HDIM; k += 256) {
        float hv = hrow[k];
        a0 += hv * W_att[k];
        a1 += hv * W_att[HDIM + k];
        a2 += hv * W_att[2 * HDIM + k];
        a3 += hv * W_att[3 * HDIM + k];
        a4 += hv * W_att[4 * HDIM + k];
    }
    #pragma unroll
    for (int o = 16; o > 0; o >>= 1) {
        a0 += __shfl_down_sync(0xffffffffu, a0, o);
        a1 += __shfl_down_sync(0xffffffffu, a1, o);
        a2 += __shfl_down_sync(0xffffffffu, a2, o);
        a3 += __shfl_down_sync(0xffffffffu, a3, o);
        a4 += __shfl_down_sync(0xffffffffu, a4, o);
    }
    int warp = tid >> 5, lane = tid & 31;
    if (lane == 0) {
        red[warp][0] = a0; red[warp][1] = a1; red[warp][2] = a2;
        red[warp][3] = a3; red[warp][4] = a4;
    }
    __syncthreads();
    if (tid < 5) {
        float s = b_att[tid];
        #pragma unroll
        for (int w = 0; w < 8; w++) s += red[w][tid];
        p[tid] = s;
    }
    __syncthreads();

    float gx     = 32.5f * (p[0] + 1.f);
    float gy     = 32.5f * (p[1] + 1.f);
    float inv2s2 = 0.5f * expf(-p[2]);
    float delta  = (63.f / 15.f) * expf(p[3]);
    float gam    = expf(p[4]);

    // ---- filterbank ----
    for (int idx = tid; idx < 1024; idx += 256) {
        int i = idx >> 6, a = idx & 63;
        float mu = (i - 8.5f) * delta;
        float dx = (float)a - (gx + mu);
        float dy = (float)a - (gy + mu);
        fx[i][a] = __expf(-dx * dx * inv2s2);
        fy[i][a] = __expf(-dy * dy * inv2s2);
    }
    __syncthreads();
    if (tid < 32) {
        float s = 0.f;
        if (tid < 16) {
            for (int a = 0; a < 64; a++) s += fx[tid][a];
        } else {
            for (int a = 0; a < 64; a++) s += fy[tid - 16][a];
        }
        rs[tid] = 1.f / (s + EPSV);
    }
    __syncthreads();
    for (int idx = tid; idx < 1024; idx += 256) {
        int i = idx >> 6, a = idx & 63;
        fx[i][a] *= rs[i];
        fy[i][a] *= rs[16 + i];
    }
    __syncthreads();

    // ---- glimpse per channel ----
    for (int c = 0; c < 3; c++) {
        const float4* img4 = (const float4*)(x + ((size_t)(b * 3 + c)) * 4096);
        float4* simg4 = (float4*)&simg[0][0];
        for (int i = tid; i < 1024; i += 256) simg4[i] = img4[i];
        __syncthreads();

        // phase 1: 4 n-outputs per thread
        {
            int a = tid & 63, ng = tid >> 6;
            float ac[4] = {0.f, 0.f, 0.f, 0.f};
            #pragma unroll 8
            for (int y = 0; y < 64; y++) {
                float iv = simg[y][a];
                #pragma unroll
                for (int q = 0; q < 4; q++) ac[q] += fy[ng * 4 + q][y] * iv;
            }
            #pragma unroll
            for (int q = 0; q < 4; q++) stmp[ng * 4 + q][a] = ac[q];
        }
        __syncthreads();

        // phase 2
        int n = tid >> 4, xx = tid & 15;
        float s = 0.f;
        #pragma unroll 8
        for (int a = 0; a < 64; a++) s += stmp[n][a] * fx[xx][a];
        float v = s * gam;
        __nv_bfloat16 vh = __float2bfloat16(v);
        size_t off = (size_t)b * KDIM + c * 256 + tid;
        g_Ah[off] = vh;
        g_Al[off] = __float2bfloat16(v - __bfloat162float(vh));
        __syncthreads();
    }
}

// ---------------- gates GEMM (mma.sync split-bf16) + fused LSTM epilogue ----------------
// C[1024,4096(perm)] = A[1024,1792] @ W^T; CTA tile 128x256, 16 warps (2x8), warp 64x32,
// BK=32, 3-stage cp.async pipeline.
#define TA 10240                 // A tile: 128 rows * 80B
#define TB 20480                 // B tile: 256 rows * 80B
#define STG (2 * TA + 2 * TB)    // 61440
#define NSTG 3
#define GSMEM (NSTG * STG + 1024)
#define NKB 56

__global__ __launch_bounds__(512, 1) void gemm_gates()
{
    extern __shared__ char smem[];
    const int tid = threadIdx.x;
    const int lane = tid & 31;
    const int wid = tid >> 5;
    const int wm = wid >> 3;          // 0..1
    const int wn = wid & 7;           // 0..7
    const int bn = blockIdx.x * 256;
    const int bm = blockIdx.y * 128;
    const int ub = bn >> 2;           // unit base (64 units per CTA)

    float* bias_s = (float*)(smem + NSTG * STG);
    if (tid < 256) bias_s[tid] = g_biasp[bn + tid];

    float acc[4][4][4];
    #pragma unroll
    for (int i = 0; i < 4; i++)
        #pragma unroll
        for (int j = 0; j < 4; j++)
            #pragma unroll
            for (int q = 0; q < 4; q++) acc[i][j][q] = 0.f;

    const uint32_t a_off = (uint32_t)((wm * 64 + (lane & 15)) * 80 + (lane >> 4) * 16);
    const uint32_t b_row = (uint32_t)(wn * 32 + (lane & 7) + ((lane >> 4) << 3));
    const uint32_t b_off = b_row * 80 + (((uint32_t)lane >> 3) & 1) * 16;

    auto issue = [&](int kb, char* buf) {
        int kcol = kb * 32;
        uint32_t bu = smem_u32(buf);
        #pragma unroll
        for (int i = 0; i < 6; i++) {
            int cid = tid + i * 512;
            const __nv_bfloat16* gp;
            uint32_t so;
            if (cid < 1024) {
                int t = cid >> 9;               // 0=AH 1=AL
                int w = cid & 511;
                int row = w >> 2, ch = w & 3;
                gp = (t ? g_Al : g_Ah) + (size_t)(bm + row) * KDIM + kcol + ch * 8;
                so = t * TA + row * 80 + ch * 16;
            } else {
                int cid2 = cid - 1024;
                int t = cid2 >> 10;             // 0=BH 1=BL
                int w = cid2 & 1023;
                int row = w >> 2, ch = w & 3;
                gp = (t ? g_Wl : g_Wh) + (size_t)(bn + row) * KDIM + kcol + ch * 8;
                so = 2 * TA + t * TB + row * 80 + ch * 16;
            }
            cpa16(bu + so, gp);
        }
    };

    issue(0, smem + 0 * STG);
    asm volatile("cp.async.commit_group;" ::: "memory");
    issue(1, smem + 1 * STG);
    asm volatile("cp.async.commit_group;" ::: "memory");

    int s_cur = 0, s_nxt = 2;
    for (int kb = 0; kb < NKB; kb++) {
        if (kb + 2 < NKB) issue(kb + 2, smem + s_nxt * STG);
        asm volatile("cp.async.commit_group;" ::: "memory");
        asm volatile("cp.async.wait_group 2;" ::: "memory");
        __syncthreads();

        uint32_t sb = smem_u32(smem + s_cur * STG);
        #pragma unroll
        for (int kh = 0; kh < 2; kh++) {
            uint32_t kadd = kh * 32;
            uint32_t aH[4][4], aL[4][4], bb[2][4];
            // hi*hi
            #pragma unroll
            for (int mt = 0; mt < 4; mt++)
                ldmx4(aH[mt], sb + a_off + mt * (16 * 80) + kadd);
            #pragma unroll
            for (int g = 0; g < 2; g++)
                ldmx4(bb[g], sb + 2 * TA + b_off + g * (16 * 80) + kadd);
            #pragma unroll
            for (int mt = 0; mt < 4; mt++)
                #pragma unroll
                for (int nt = 0; nt < 4; nt++)
                    mma16816(acc[mt][nt], aH[mt], &bb[nt >> 1][(nt & 1) * 2]);
            // lo*hi (bb still holds bH)
            #pragma unroll
            for (int mt = 0; mt < 4; mt++)
                ldmx4(aL[mt], sb + TA + a_off + mt * (16 * 80) + kadd);
            #pragma unroll
            for (int mt = 0; mt < 4; mt++)
                #pragma unroll
                for (int nt = 0; nt < 4; nt++)
                    mma16816(acc[mt][nt], aL[mt], &bb[nt >> 1][(nt & 1) * 2]);
            // hi*lo (reload bb with bL)
            #pragma unroll
            for (int g = 0; g < 2; g++)
                ldmx4(bb[g], sb + 2 * TA + TB + b_off + g * (16 * 80) + kadd);
            #pragma unroll
            for (int mt = 0; mt < 4; mt++)
                #pragma unroll
                for (int nt = 0; nt < 4; nt++)
                    mma16816(acc[mt][nt], aH[mt], &bb[nt >> 1][(nt & 1) * 2]);
        }
        __syncthreads();
        s_cur = (s_cur == 2) ? 0 : s_cur + 1;
        s_nxt = (s_nxt == 2) ? 0 : s_nxt + 1;
    }

    // ---------- fused LSTM epilogue (smem-staged) ----------
    float* c_s = (float*)smem;                 // [128][65]
    float* h_s = (float*)(smem + 33536);       // [128][65]

    for (int i = tid; i < 8192; i += 512) {
        int row = i >> 6, u = i & 63;
        c_s[row * 65 + u] = g_c[(size_t)(bm + row) * HDIM + ub + u];
    }
    __syncthreads();

    #pragma unroll
    for (int mt = 0; mt < 4; mt++) {
        #pragma unroll
        for (int nt = 0; nt < 4; nt++) {
            int colbase = wn * 32 + nt * 8 + (lane & 3) * 2;
            float b0 = bias_s[colbase], b1 = bias_s[colbase + 1];
            #pragma unroll
            for (int half = 0; half < 2; half++) {
                float v0 = acc[mt][nt][half * 2 + 0] + b0;
                float v1 = acc[mt][nt][half * 2 + 1] + b1;
                float p0 = __shfl_xor_sync(0xffffffffu, v0, 1);
                float p1 = __shfl_xor_sync(0xffffffffu, v1, 1);
                if (!(lane & 1)) {
                    // v0=i, v1=f, p0=g, p1=o
                    int rowl = wm * 64 + mt * 16 + (lane >> 2) + half * 8;
                    int uc = (colbase >> 2);
                    float ig = sigm(v0);
                    float fg = sigm(v1);
                    float gg = tanhfast(p0);
                    float og = sigm(p1);
                    float cn = fg * c_s[rowl * 65 + uc] + ig * gg;
                    c_s[rowl * 65 + uc] = cn;
                    h_s[rowl * 65 + uc] = og * tanhfast(cn);
                }
            }
        }
    }
    __syncthreads();

    for (int i = tid; i < 8192; i += 512) {
        int row = i >> 6, u = i & 63;
        float cn = c_s[row * 65 + u];
        float hn = h_s[row * 65 + u];
        size_t ro = (size_t)(bm + row);
        g_c[ro * HDIM + ub + u] = cn;
        g_h[ro * HDIM + ub + u] = hn;
        __nv_bfloat16 hh = __float2bfloat16(hn);
        g_Ah[ro * KDIM + 768 + ub + u] = hh;
        g_Al[ro * KDIM + 768 + ub + u] = __float2bfloat16(hn - __bfloat162float(hh));
    }
}

// ---------------- fc0 GEMM (mma.sync split-bf16): t = relu(h @ W_fc0^T + b) ----------------
// A = h-part of g_Ah/g_Al (cols 768..1791), K=1024. CTA tile 128x128, 256 thr, warp 64x32.
#define FTA 10240
#define FSTG (4 * FTA)           // 40960
#define FSMEM (3 * FSTG + 256)
#define FNKB 32

__global__ __launch_bounds__(256, 1) void gemm_fc0(const float* __restrict__ bias)
{
    extern __shared__ char smem[];
    const int tid = threadIdx.x;
    const int lane = tid & 31;
    const int wid = tid >> 5;
    const int wm = wid >> 2;          // 0..1
    const int wn = wid & 3;           // 0..3
    const int bn = blockIdx.x * 128;
    const int bm = blockIdx.y * 128;

    float acc[4][4][4];
    #pragma unroll
    for (int i = 0; i < 4; i++)
        #pragma unroll
        for (int j = 0; j < 4; j++)
            #pragma unroll
            for (int q = 0; q < 4; q++) acc[i][j][q] = 0.f;

    const uint32_t a_off = (uint32_t)((wm * 64 + (lane & 15)) * 80 + (lane >> 4) * 16);
    const uint32_t b_row = (uint32_t)(wn * 32 + (lane & 7) + ((lane >> 4) << 3));
    const uint32_t b_off = b_row * 80 + (((uint32_t)lane >> 3) & 1) * 16;

    auto issue = [&](int kb, char* buf) {
        int kcol = kb * 32;
        uint32_t bu = smem_u32(buf);
        #pragma unroll
        for (int i = 0; i < 8; i++) {
            int cid = tid + i * 256;
            int t4 = cid >> 9;                // 0=AH 1=AL 2=BH 3=BL
            int w = cid & 511;
            int row = w >> 2, ch = w & 3;
            const __nv_bfloat16* gp;
            if (t4 == 0)      gp = g_Ah + (size_t)(bm + row) * KDIM + 768 + kcol + ch * 8;
            else if (t4 == 1) gp = g_Al + (size_t)(bm + row) * KDIM + 768 + kcol + ch * 8;
            else if (t4 == 2) gp = g_Fh + (size_t)(bn + row) * HDIM + kcol + ch * 8;
            else              gp = g_Fl + (size_t)(bn + row) * HDIM + kcol + ch * 8;
            cpa16(bu + t4 * FTA + row * 80 + ch * 16, gp);
        }
    };

    issue(0, smem + 0 * FSTG);
    asm volatile("cp.async.commit_group;" ::: "memory");
    issue(1, smem + 1 * FSTG);
    asm volatile("cp.async.commit_group;" ::: "memory");

    int s_cur = 0, s_nxt = 2;
    for (int kb = 0; kb < FNKB; kb++) {
        if (kb + 2 < FNKB) issue(kb + 2, smem + s_nxt * FSTG);
        asm volatile("cp.async.commit_group;" ::: "memory");
        asm volatile("cp.async.wait_group 2;" ::: "memory");
        __syncthreads();

        uint32_t sb = smem_u32(smem + s_cur * FSTG);
        #pragma unroll
        for (int kh = 0; kh < 2; kh++) {
            uint32_t kadd = kh * 32;
            uint32_t aH[4][4], aL[4][4], bb[2][4];
            #pragma unroll
            for (int mt = 0; mt < 4; mt++)
                ldmx4(aH[mt], sb + a_off + mt * (16 * 80) + kadd);
            #pragma unroll
            for (int g = 0; g < 2; g++)
                ldmx4(bb[g], sb + 2 * FTA + b_off + g * (16 * 80) + kadd);
            #pragma unroll
            for (int mt = 0; mt < 4; mt++)
                #pragma unroll
                for (int nt = 0; nt < 4; nt++)
                    mma16816(acc[mt][nt], aH[mt], &bb[nt >> 1][(nt & 1) * 2]);
            #pragma unroll
            for (int mt = 0; mt < 4; mt++)
                ldmx4(aL[mt], sb + FTA + a_off + mt * (16 * 80) + kadd);
            #pragma unroll
            for (int mt = 0; mt < 4; mt++)
                #pragma unroll
                for (int nt = 0; nt < 4; nt++)
                    mma16816(acc[mt][nt], aL[mt], &bb[nt >> 1][(nt & 1) * 2]);
            #pragma unroll
            for (int g = 0; g < 2; g++)
                ldmx4(bb[g], sb + 3 * FTA + b_off + g * (16 * 80) + kadd);
            #pragma unroll
            for (int mt = 0; mt < 4; mt++)
                #pragma unroll
                for (int nt = 0; nt < 4; nt++)
                    mma16816(acc[mt][nt], aH[mt], &bb[nt >> 1][(nt & 1) * 2]);
        }
        __syncthreads();
        s_cur = (s_cur == 2) ? 0 : s_cur + 1;
        s_nxt = (s_nxt == 2) ? 0 : s_nxt + 1;
    }

    #pragma unroll
    for (int mt = 0; mt < 4; mt++) {
        int r0 = bm + wm * 64 + mt * 16 + (lane >> 2);
        #pragma unroll
        for (int nt = 0; nt < 4; nt++) {
            int c0 = bn + wn * 32 + nt * 8 + (lane & 3) * 2;
            float b0 = bias[c0], b1 = bias[c0 + 1];
            float v0 = fmaxf(acc[mt][nt][0] + b0, 0.f);
            float v1 = fmaxf(acc[mt][nt][1] + b1, 0.f);
            float v2 = fmaxf(acc[mt][nt][2] + b0, 0.f);
            float v3 = fmaxf(acc[mt][nt][3] + b1, 0.f);
            *(float2*)&g_t[(size_t)r0 * HDIM + c0] = make_float2(v0, v1);
            *(float2*)&g_t[(size_t)(r0 + 8) * HDIM + c0] = make_float2(v2, v3);
        }
    }
}

// ---------------- final small FC ----------------
__global__ __launch_bounds__(256) void fc_out(
    const float* __restrict__ W, const float* __restrict__ bias, float* __restrict__ out)
{
    int b = blockIdx.x;
    int tid = threadIdx.x;
    const float* trow = g_t + (size_t)b * HDIM;
    float acc[10];
    #pragma unroll
    for (int j = 0; j < 10; j++) acc[j] = 0.f;
    for (int k = tid; k < HDIM; k += 256) {
        float tv = trow[k];
        #pragma unroll
        for (int j = 0; j < 10; j++) acc[j] += tv * W[j * HDIM + k];
    }
    #pragma unroll
    for (int j = 0; j < 10; j++)
        #pragma unroll
        for (int o = 16; o > 0; o >>= 1)
            acc[j] += __shfl_down_sync(0xffffffffu, acc[j], o);
    __shared__ float red[8][10];
    int warp = tid >> 5, lane = tid & 31;
    if (lane == 0)
        #pragma unroll
        for (int j = 0; j < 10; j++) red[warp][j] = acc[j];
    __syncthreads();
    if (tid < 10) {
        float s = bias[tid];
        #pragma unroll
        for (int w = 0; w < 8; w++) s += red[w][tid];
        out[b * 10 + tid] = s;
    }
}

// ---------------- launcher ----------------
extern "C" void kernel_launch(void* const* d_in, const int* in_sizes, int n_in,
                              void* d_out, int out_size)
{
    const float* x      = (const float*)d_in[0];
    const float* W_att  = (const float*)d_in[1];
    const float* b_att  = (const float*)d_in[2];
    const float* W_ih   = (const float*)d_in[3];
    const float* W_hh   = (const float*)d_in[4];
    const float* b_ih   = (const float*)d_in[5];
    const float* b_hh   = (const float*)d_in[6];
    const float* W_fc0  = (const float*)d_in[7];
    const float* b_fc0  = (const float*)d_in[8];
    const float* W_fc   = (const float*)d_in[9];
    const float* b_fc   = (const float*)d_in[10];
    float* out = (float*)d_out;

    cudaFuncSetAttribute(gemm_gates, cudaFuncAttributeMaxDynamicSharedMemorySize, GSMEM);
    cudaFuncSetAttribute(gemm_fc0,   cudaFuncAttributeMaxDynamicSharedMemorySize, FSMEM);

    convert_weights<<<GATES, 256>>>(W_ih, W_hh, b_ih, b_hh);
    convert_wfc0<<<HDIM, 256>>>(W_fc0);
    zero_state<<<(BATCH * HDIM) / 256, 256>>>();

    for (int t = 0; t < 16; t++) {
        att_glimpse<<<BATCH, 256>>>(x, W_att, b_att);
        gemm_gates<<<dim3(GATES / 256, BATCH / 128), 512, GSMEM>>>();
    }

    gemm_fc0<<<dim3(HDIM / 128, BATCH / 128), 256, FSMEM>>>(b_fc0);
    fc_out<<<BATCH, 256>>>(W_fc, b_fc, out);
}

// round 9
// speedup vs baseline: 1.4027x; 1.4027x over previous
#include <cuda_runtime.h>
#include <cuda_bf16.h>
#include <math.h>
#include <stdint.h>

#define BATCH 1024
#define HDIM  1024
#define GATES 4096
#define INDIM 768
#define KDIM  1792
#define EPSV  1e-8f

// ---------------- scratch (no allocations allowed) ----------------
__device__ float g_h[BATCH * HDIM];
__device__ float g_c[BATCH * HDIM];
__device__ float g_t[BATCH * HDIM];
__device__ float g_biasp[GATES];
__device__ __align__(16) __nv_bfloat16 g_Ah[BATCH * KDIM];
__device__ __align__(16) __nv_bfloat16 g_Al[BATCH * KDIM];
__device__ __align__(16) __nv_bfloat16 g_Wh[(size_t)GATES * KDIM];
__device__ __align__(16) __nv_bfloat16 g_Wl[(size_t)GATES * KDIM];
__device__ __align__(16) __nv_bfloat16 g_Fh[(size_t)HDIM * HDIM];
__device__ __align__(16) __nv_bfloat16 g_Fl[(size_t)HDIM * HDIM];

// ---------------- helpers ----------------
__device__ __forceinline__ uint32_t smem_u32(const void* p) {
    uint32_t a;
    asm("{ .reg .u64 t; cvta.to.shared.u64 t, %1; cvt.u32.u64 %0, t; }" : "=r"(a) : "l"(p));
    return a;
}
static __device__ __forceinline__ void cpa16(uint32_t s, const void* g) {
    asm volatile("cp.async.cg.shared.global [%0], [%1], 16;" :: "r"(s), "l"(g));
}
static __device__ __forceinline__ void ldmx4(uint32_t* r, uint32_t addr) {
    asm volatile("ldmatrix.sync.aligned.m8n8.x4.shared.b16 {%0,%1,%2,%3}, [%4];"
                 : "=r"(r[0]), "=r"(r[1]), "=r"(r[2]), "=r"(r[3]) : "r"(addr));
}
static __device__ __forceinline__ void mma16816(float* d, const uint32_t* a, const uint32_t* b) {
    asm volatile(
        "mma.sync.aligned.m16n8k16.row.col.f32.bf16.bf16.f32 "
        "{%0,%1,%2,%3}, {%4,%5,%6,%7}, {%8,%9}, {%0,%1,%2,%3};"
        : "+f"(d[0]), "+f"(d[1]), "+f"(d[2]), "+f"(d[3])
        : "r"(a[0]), "r"(a[1]), "r"(a[2]), "r"(a[3]), "r"(b[0]), "r"(b[1]));
}
static __device__ __forceinline__ float sigm(float v) { return 1.f / (1.f + __expf(-v)); }
static __device__ __forceinline__ float tanhfast(float v) { return 2.f / (1.f + __expf(-2.f * v)) - 1.f; }

// ---------------- init ----------------
__global__ void zero_state() {
    int idx = blockIdx.x * 256 + threadIdx.x;
    g_h[idx] = 0.f;
    g_c[idx] = 0.f;
    int row = idx >> 10, j = idx & 1023;
    __nv_bfloat16 z = __float2bfloat16(0.f);
    g_Ah[(size_t)row * KDIM + 768 + j] = z;
    g_Al[(size_t)row * KDIM + 768 + j] = z;
}

// ---------------- weight convert: (unit,gate) interleave permutation + bf16 split ----------------
__global__ __launch_bounds__(256) void convert_weights(
    const float* __restrict__ W_ih, const float* __restrict__ W_hh,
    const float* __restrict__ b_ih, const float* __restrict__ b_hh)
{
    int pc = blockIdx.x;                    // permuted row: unit = pc>>2, gate = pc&3
    int orig = (pc & 3) * 1024 + (pc >> 2);
    for (int c = threadIdx.x; c < KDIM; c += 256) {
        float w = (c < 768) ? W_ih[(size_t)orig * 768 + c]
                            : W_hh[(size_t)orig * 1024 + (c - 768)];
        __nv_bfloat16 wh = __float2bfloat16(w);
        g_Wh[(size_t)pc * KDIM + c] = wh;
        g_Wl[(size_t)pc * KDIM + c] = __float2bfloat16(w - __bfloat162float(wh));
    }
    if (threadIdx.x == 0) g_biasp[pc] = b_ih[orig] + b_hh[orig];
}

__global__ __launch_bounds__(256) void convert_wfc0(const float* __restrict__ W_fc0) {
    int r = blockIdx.x;
    for (int c = threadIdx.x; c < HDIM; c += 256) {
        float w = W_fc0[(size_t)r * HDIM + c];
        __nv_bfloat16 wh = __float2bfloat16(w);
        g_Fh[(size_t)r * HDIM + c] = wh;
        g_Fl[(size_t)r * HDIM + c] = __float2bfloat16(w - __bfloat162float(wh));
    }
}

// ---------------- fused attention + filterbank + glimpse ----------------
__global__ __launch_bounds__(256) void att_glimpse(
    const float* __restrict__ x,
    const float* __restrict__ W_att, const float* __restrict__ b_att)
{
    int b = blockIdx.x;
    int tid = threadIdx.x;

    __shared__ float fx[16][65];
    __shared__ float fy[16][65];
    __shared__ float simg[64][64];
    __shared__ float stmp[16][64];
    __shared__ float red[8][5];
    __shared__ float p[5];
    __shared__ float rs[32];

    // ---- attention params: p = h @ W_att^T + b_att ----
    const float* hrow = g_h + (size_t)b * HDIM;
    float a0 = 0.f, a1 = 0.f, a2 = 0.f, a3 = 0.f, a4 = 0.f;
    for (int k = tid; k < HDIM; k += 256) {
        float hv = hrow[k];
        a0 += hv * W_att[k];
        a1 += hv * W_att[HDIM + k];
        a2 += hv * W_att[2 * HDIM + k];
        a3 += hv * W_att[3 * HDIM + k];
        a4 += hv * W_att[4 * HDIM + k];
    }
    #pragma unroll
    for (int o = 16; o > 0; o >>= 1) {
        a0 += __shfl_down_sync(0xffffffffu, a0, o);
        a1 += __shfl_down_sync(0xffffffffu, a1, o);
        a2 += __shfl_down_sync(0xffffffffu, a2, o);
        a3 += __shfl_down_sync(0xffffffffu, a3, o);
        a4 += __shfl_down_sync(0xffffffffu, a4, o);
    }
    int warp = tid >> 5, lane = tid & 31;
    if (lane == 0) {
        red[warp][0] = a0; red[warp][1] = a1; red[warp][2] = a2;
        red[warp][3] = a3; red[warp][4] = a4;
    }
    __syncthreads();
    if (tid < 5) {
        float s = b_att[tid];
        #pragma unroll
        for (int w = 0; w < 8; w++) s += red[w][tid];
        p[tid] = s;
    }
    __syncthreads();

    float gx     = 32.5f * (p[0] + 1.f);
    float gy     = 32.5f * (p[1] + 1.f);
    float inv2s2 = 0.5f * expf(-p[2]);
    float delta  = (63.f / 15.f) * expf(p[3]);
    float gam    = expf(p[4]);

    // ---- filterbank ----
    for (int idx = tid; idx < 1024; idx += 256) {
        int i = idx >> 6, a = idx & 63;
        float mu = (i - 8.5f) * delta;
        float dx = (float)a - (gx + mu);
        float dy = (float)a - (gy + mu);
        fx[i][a] = __expf(-dx * dx * inv2s2);
        fy[i][a] = __expf(-dy * dy * inv2s2);
    }
    __syncthreads();
    if (tid < 32) {
        float s = 0.f;
        if (tid < 16) {
            for (int a = 0; a < 64; a++) s += fx[tid][a];
        } else {
            for (int a = 0; a < 64; a++) s += fy[tid - 16][a];
        }
        rs[tid] = 1.f / (s + EPSV);
    }
    __syncthreads();
    for (int idx = tid; idx < 1024; idx += 256) {
        int i = idx >> 6, a = idx & 63;
        fx[i][a] *= rs[i];
        fy[i][a] *= rs[16 + i];
    }
    __syncthreads();

    // ---- glimpse per channel ----
    for (int c = 0; c < 3; c++) {
        const float4* img4 = (const float4*)(x + ((size_t)(b * 3 + c)) * 4096);
        float4* simg4 = (float4*)&simg[0][0];
        for (int i = tid; i < 1024; i += 256) simg4[i] = img4[i];
        __syncthreads();

        // phase 1: 4 n-outputs per thread
        {
            int a = tid & 63, ng = tid >> 6;
            float ac[4] = {0.f, 0.f, 0.f, 0.f};
            #pragma unroll 8
            for (int y = 0; y < 64; y++) {
                float iv = simg[y][a];
                #pragma unroll
                for (int q = 0; q < 4; q++) ac[q] += fy[ng * 4 + q][y] * iv;
            }
            #pragma unroll
            for (int q = 0; q < 4; q++) stmp[ng * 4 + q][a] = ac[q];
        }
        __syncthreads();

        // phase 2
        int n = tid >> 4, xx = tid & 15;
        float s = 0.f;
        #pragma unroll 8
        for (int a = 0; a < 64; a++) s += stmp[n][a] * fx[xx][a];
        float v = s * gam;
        __nv_bfloat16 vh = __float2bfloat16(v);
        size_t off = (size_t)b * KDIM + c * 256 + tid;
        g_Ah[off] = vh;
        g_Al[off] = __float2bfloat16(v - __bfloat162float(vh));
        __syncthreads();
    }
}

// ---------------- gates GEMM (mma.sync split-bf16) + fused LSTM epilogue ----------------
// R5-proven config: CTA tile 128x256, 256 thr (8 warps, 2x4), warp tile 64x64,
// BK=32, 3-stage cp.async pipeline.
#define TA 10240                 // A tile: 128 rows * 80B
#define TB 20480                 // B tile: 256 rows * 80B
#define STG (2 * TA + 2 * TB)    // 61440
#define NSTG 3
#define GSMEM (NSTG * STG + 1024)
#define NKB 56

__global__ __launch_bounds__(256, 1) void gemm_gates()
{
    extern __shared__ char smem[];
    const int tid = threadIdx.x;
    const int lane = tid & 31;
    const int wid = tid >> 5;
    const int wm = wid >> 2;          // 0..1
    const int wn = wid & 3;           // 0..3
    const int bn = blockIdx.x * 256;
    const int bm = blockIdx.y * 128;
    const int ub = bn >> 2;           // unit base (64 units per CTA)

    float* bias_s = (float*)(smem + NSTG * STG);
    for (int i = tid; i < 256; i += 256) bias_s[i] = g_biasp[bn + i];

    float acc[4][8][4];
    #pragma unroll
    for (int i = 0; i < 4; i++)
        #pragma unroll
        for (int j = 0; j < 8; j++)
            #pragma unroll
            for (int q = 0; q < 4; q++) acc[i][j][q] = 0.f;

    const uint32_t a_off = (uint32_t)((wm * 64 + (lane & 15)) * 80 + (lane >> 4) * 16);
    const uint32_t b_row = (uint32_t)(wn * 64 + (lane & 7) + ((lane >> 4) << 3));
    const uint32_t b_off = b_row * 80 + (((uint32_t)lane >> 3) & 1) * 16;

    auto issue = [&](int kb, char* buf) {
        int kcol = kb * 32;
        uint32_t bu = smem_u32(buf);
        #pragma unroll
        for (int i = 0; i < 12; i++) {
            int cid = tid + i * 256;
            const __nv_bfloat16* gp;
            uint32_t so;
            if (cid < 1024) {
                int t = cid >> 9;               // 0=AH 1=AL
                int w = cid & 511;
                int row = w >> 2, ch = w & 3;
                gp = (t ? g_Al : g_Ah) + (size_t)(bm + row) * KDIM + kcol + ch * 8;
                so = t * TA + row * 80 + ch * 16;
            } else {
                int cid2 = cid - 1024;
                int t = cid2 >> 10;             // 0=BH 1=BL
                int w = cid2 & 1023;
                int row = w >> 2, ch = w & 3;
                gp = (t ? g_Wl : g_Wh) + (size_t)(bn + row) * KDIM + kcol + ch * 8;
                so = 2 * TA + t * TB + row * 80 + ch * 16;
            }
            cpa16(bu + so, gp);
        }
    };

    issue(0, smem + 0 * STG);
    asm volatile("cp.async.commit_group;" ::: "memory");
    issue(1, smem + 1 * STG);
    asm volatile("cp.async.commit_group;" ::: "memory");

    int s_cur = 0, s_nxt = 2;
    for (int kb = 0; kb < NKB; kb++) {
        if (kb + 2 < NKB) issue(kb + 2, smem + s_nxt * STG);
        asm volatile("cp.async.commit_group;" ::: "memory");
        asm volatile("cp.async.wait_group 2;" ::: "memory");
        __syncthreads();

        uint32_t sb = smem_u32(smem + s_cur * STG);
        #pragma unroll
        for (int kh = 0; kh < 2; kh++) {
            uint32_t kadd = kh * 32;
            uint32_t aH[4][4], aL[4][4], bH[4][4], bL[4][4];
            #pragma unroll
            for (int mt = 0; mt < 4; mt++)
                ldmx4(aH[mt], sb + a_off + mt * (16 * 80) + kadd);
            #pragma unroll
            for (int g = 0; g < 4; g++)
                ldmx4(bH[g], sb + 2 * TA + b_off + g * (16 * 80) + kadd);

            #pragma unroll
            for (int mt = 0; mt < 4; mt++)
                #pragma unroll
                for (int nt = 0; nt < 8; nt++)
                    mma16816(acc[mt][nt], aH[mt], &bH[nt >> 1][(nt & 1) * 2]);

            #pragma unroll
            for (int g = 0; g < 4; g++)
                ldmx4(bL[g], sb + 2 * TA + TB + b_off + g * (16 * 80) + kadd);
            #pragma unroll
            for (int mt = 0; mt < 4; mt++)
                #pragma unroll
                for (int nt = 0; nt < 8; nt++)
                    mma16816(acc[mt][nt], aH[mt], &bL[nt >> 1][(nt & 1) * 2]);

            #pragma unroll
            for (int mt = 0; mt < 4; mt++)
                ldmx4(aL[mt], sb + TA + a_off + mt * (16 * 80) + kadd);
            #pragma unroll
            for (int mt = 0; mt < 4; mt++)
                #pragma unroll
                for (int nt = 0; nt < 8; nt++)
                    mma16816(acc[mt][nt], aL[mt], &bH[nt >> 1][(nt & 1) * 2]);
        }
        __syncthreads();
        s_cur = (s_cur == 2) ? 0 : s_cur + 1;
        s_nxt = (s_nxt == 2) ? 0 : s_nxt + 1;
    }

    // ---------- fused LSTM epilogue (smem-staged for coalescing) ----------
    float* c_s = (float*)smem;                 // [128][65]
    float* h_s = (float*)(smem + 33536);       // [128][65]

    for (int i = tid; i < 8192; i += 256) {
        int row = i >> 6, u = i & 63;
        c_s[row * 65 + u] = g_c[(size_t)(bm + row) * HDIM + ub + u];
    }
    __syncthreads();

    #pragma unroll
    for (int mt = 0; mt < 4; mt++) {
        #pragma unroll
        for (int nt = 0; nt < 8; nt++) {
            int colbase = wn * 64 + nt * 8 + (lane & 3) * 2;
            float b0 = bias_s[colbase], b1 = bias_s[colbase + 1];
            #pragma unroll
            for (int half = 0; half < 2; half++) {
                float v0 = acc[mt][nt][half * 2 + 0] + b0;
                float v1 = acc[mt][nt][half * 2 + 1] + b1;
                float p0 = __shfl_xor_sync(0xffffffffu, v0, 1);
                float p1 = __shfl_xor_sync(0xffffffffu, v1, 1);
                if (!(lane & 1)) {
                    // v0=i, v1=f, p0=g, p1=o
                    int rowl = wm * 64 + mt * 16 + (lane >> 2) + half * 8;
                    int uc = (colbase >> 2);   // local unit 0..63
                    float ig = sigm(v0);
                    float fg = sigm(v1);
                    float gg = tanhfast(p0);
                    float og = sigm(p1);
                    float cn = fg * c_s[rowl * 65 + uc] + ig * gg;
                    c_s[rowl * 65 + uc] = cn;
                    h_s[rowl * 65 + uc] = og * tanhfast(cn);
                }
            }
        }
    }
    __syncthreads();

    // write out coalesced: c, h, Ah, Al
    for (int i = tid; i < 8192; i += 256) {
        int row = i >> 6, u = i & 63;
        float cn = c_s[row * 65 + u];
        float hn = h_s[row * 65 + u];
        size_t ro = (size_t)(bm + row);
        g_c[ro * HDIM + ub + u] = cn;
        g_h[ro * HDIM + ub + u] = hn;
        __nv_bfloat16 hh = __float2bfloat16(hn);
        g_Ah[ro * KDIM + 768 + ub + u] = hh;
        g_Al[ro * KDIM + 768 + ub + u] = __float2bfloat16(hn - __bfloat162float(hh));
    }
}

// ---------------- fc0 GEMM (mma.sync split-bf16): t = relu(h @ W_fc0^T + b) ----------------
// A = h-part of g_Ah/g_Al (cols 768..1791), K=1024. CTA tile 128x128, 256 thr, warp 64x32.
#define FTA 10240
#define FSTG (4 * FTA)           // 40960
#define FSMEM (3 * FSTG + 256)
#define FNKB 32

__global__ __launch_bounds__(256, 1) void gemm_fc0(const float* __restrict__ bias)
{
    extern __shared__ char smem[];
    const int tid = threadIdx.x;
    const int lane = tid & 31;
    const int wid = tid >> 5;
    const int wm = wid >> 2;          // 0..1
    const int wn = wid & 3;           // 0..3
    const int bn = blockIdx.x * 128;
    const int bm = blockIdx.y * 128;

    float acc[4][4][4];
    #pragma unroll
    for (int i = 0; i < 4; i++)
        #pragma unroll
        for (int j = 0; j < 4; j++)
            #pragma unroll
            for (int q = 0; q < 4; q++) acc[i][j][q] = 0.f;

    const uint32_t a_off = (uint32_t)((wm * 64 + (lane & 15)) * 80 + (lane >> 4) * 16);
    const uint32_t b_row = (uint32_t)(wn * 32 + (lane & 7) + ((lane >> 4) << 3));
    const uint32_t b_off = b_row * 80 + (((uint32_t)lane >> 3) & 1) * 16;

    auto issue = [&](int kb, char* buf) {
        int kcol = kb * 32;
        uint32_t bu = smem_u32(buf);
        #pragma unroll
        for (int i = 0; i < 8; i++) {
            int cid = tid + i * 256;
            int t4 = cid >> 9;                // 0=AH 1=AL 2=BH 3=BL
            int w = cid & 511;
            int row = w >> 2, ch = w & 3;
            const __nv_bfloat16* gp;
            if (t4 == 0)      gp = g_Ah + (size_t)(bm + row) * KDIM + 768 + kcol + ch * 8;
            else if (t4 == 1) gp = g_Al + (size_t)(bm + row) * KDIM + 768 + kcol + ch * 8;
            else if (t4 == 2) gp = g_Fh + (size_t)(bn + row) * HDIM + kcol + ch * 8;
            else              gp = g_Fl + (size_t)(bn + row) * HDIM + kcol + ch * 8;
            cpa16(bu + t4 * FTA + row * 80 + ch * 16, gp);
        }
    };

    issue(0, smem + 0 * FSTG);
    asm volatile("cp.async.commit_group;" ::: "memory");
    issue(1, smem + 1 * FSTG);
    asm volatile("cp.async.commit_group;" ::: "memory");

    int s_cur = 0, s_nxt = 2;
    for (int kb = 0; kb < FNKB; kb++) {
        if (kb + 2 < FNKB) issue(kb + 2, smem + s_nxt * FSTG);
        asm volatile("cp.async.commit_group;" ::: "memory");
        asm volatile("cp.async.wait_group 2;" ::: "memory");
        __syncthreads();

        uint32_t sb = smem_u32(smem + s_cur * FSTG);
        #pragma unroll
        for (int kh = 0; kh < 2; kh++) {
            uint32_t kadd = kh * 32;
            uint32_t aH[4][4], aL[4][4], bb[2][4];
            #pragma unroll
            for (int mt = 0; mt < 4; mt++)
                ldmx4(aH[mt], sb + a_off + mt * (16 * 80) + kadd);
            #pragma unroll
            for (int g = 0; g < 2; g++)
                ldmx4(bb[g], sb + 2 * FTA + b_off + g * (16 * 80) + kadd);
            #pragma unroll
            for (int mt = 0; mt < 4; mt++)
                #pragma unroll
                for (int nt = 0; nt < 4; nt++)
                    mma16816(acc[mt][nt], aH[mt], &bb[nt >> 1][(nt & 1) * 2]);
            #pragma unroll
            for (int mt = 0; mt < 4; mt++)
                ldmx4(aL[mt], sb + FTA + a_off + mt * (16 * 80) + kadd);
            #pragma unroll
            for (int mt = 0; mt < 4; mt++)
                #pragma unroll
                for (int nt = 0; nt < 4; nt++)
                    mma16816(acc[mt][nt], aL[mt], &bb[nt >> 1][(nt & 1) * 2]);
            #pragma unroll
            for (int g = 0; g < 2; g++)
                ldmx4(bb[g], sb + 3 * FTA + b_off + g * (16 * 80) + kadd);
            #pragma unroll
            for (int mt = 0; mt < 4; mt++)
                #pragma unroll
                for (int nt = 0; nt < 4; nt++)
                    mma16816(acc[mt][nt], aH[mt], &bb[nt >> 1][(nt & 1) * 2]);
        }
        __syncthreads();
        s_cur = (s_cur == 2) ? 0 : s_cur + 1;
        s_nxt = (s_nxt == 2) ? 0 : s_nxt + 1;
    }

    #pragma unroll
    for (int mt = 0; mt < 4; mt++) {
        int r0 = bm + wm * 64 + mt * 16 + (lane >> 2);
        #pragma unroll
        for (int nt = 0; nt < 4; nt++) {
            int c0 = bn + wn * 32 + nt * 8 + (lane & 3) * 2;
            float b0 = bias[c0], b1 = bias[c0 + 1];
            float v0 = fmaxf(acc[mt][nt][0] + b0, 0.f);
            float v1 = fmaxf(acc[mt][nt][1] + b1, 0.f);
            float v2 = fmaxf(acc[mt][nt][2] + b0, 0.f);
            float v3 = fmaxf(acc[mt][nt][3] + b1, 0.f);
            *(float2*)&g_t[(size_t)r0 * HDIM + c0] = make_float2(v0, v1);
            *(float2*)&g_t[(size_t)(r0 + 8) * HDIM + c0] = make_float2(v2, v3);
        }
    }
}

// ---------------- final small FC ----------------
__global__ __launch_bounds__(256) void fc_out(
    const float* __restrict__ W, const float* __restrict__ bias, float* __restrict__ out)
{
    int b = blockIdx.x;
    int tid = threadIdx.x;
    const float* trow = g_t + (size_t)b * HDIM;
    float acc[10];
    #pragma unroll
    for (int j = 0; j < 10; j++) acc[j] = 0.f;
    for (int k = tid; k < HDIM; k += 256) {
        float tv = trow[k];
        #pragma unroll
        for (int j = 0; j < 10; j++) acc[j] += tv * W[j * HDIM + k];
    }
    #pragma unroll
    for (int j = 0; j < 10; j++)
        #pragma unroll
        for (int o = 16; o > 0; o >>= 1)
            acc[j] += __shfl_down_sync(0xffffffffu, acc[j], o);
    __shared__ float red[8][10];
    int warp = tid >> 5, lane = tid & 31;
    if (lane == 0)
        #pragma unroll
        for (int j = 0; j < 10; j++) red[warp][j] = acc[j];
    __syncthreads();
    if (tid < 10) {
        float s = bias[tid];
        #pragma unroll
        for (int w = 0; w < 8; w++) s += red[w][tid];
        out[b * 10 + tid] = s;
    }
}

// ---------------- launcher ----------------
extern "C" void kernel_launch(void* const* d_in, const int* in_sizes, int n_in,
                              void* d_out, int out_size)
{
    const float* x      = (const float*)d_in[0];
    const float* W_att  = (const float*)d_in[1];
    const float* b_att  = (const float*)d_in[2];
    const float* W_ih   = (const float*)d_in[3];
    const float* W_hh   = (const float*)d_in[4];
    const float* b_ih   = (const float*)d_in[5];
    const float* b_hh   = (const float*)d_in[6];
    const float* W_fc0  = (const float*)d_in[7];
    const float* b_fc0  = (const float*)d_in[8];
    const float* W_fc   = (const float*)d_in[9];
    const float* b_fc   = (const float*)d_in[10];
    float* out = (float*)d_out;

    cudaFuncSetAttribute(gemm_gates, cudaFuncAttributeMaxDynamicSharedMemorySize, GSMEM);
    cudaFuncSetAttribute(gemm_fc0,   cudaFuncAttributeMaxDynamicSharedMemorySize, FSMEM);

    convert_weights<<<GATES, 256>>>(W_ih, W_hh, b_ih, b_hh);
    convert_wfc0<<<HDIM, 256>>>(W_fc0);
    zero_state<<<(BATCH * HDIM) / 256, 256>>>();

    for (int t = 0; t < 16; t++) {
        att_glimpse<<<BATCH, 256>>>(x, W_att, b_att);
        gemm_gates<<<dim3(GATES / 256, BATCH / 128), 256, GSMEM>>>();
    }

    gemm_fc0<<<dim3(HDIM / 128, BATCH / 128), 256, FSMEM>>>(b_fc0);
    fc_out<<<BATCH, 256>>>(W_fc, b_fc, out);
}

// round 10
// speedup vs baseline: 1.4211x; 1.0131x over previous
#include <cuda_runtime.h>
#include <cuda_bf16.h>
#include <math.h>
#include <stdint.h>

#define BATCH 1024
#define HDIM  1024
#define GATES 4096
#define INDIM 768
#define KDIM  1792
#define EPSV  1e-8f

// ---------------- scratch (no allocations allowed) ----------------
__device__ float g_h[BATCH * HDIM];
__device__ float g_c[BATCH * HDIM];
__device__ float g_t[BATCH * HDIM];
__device__ float g_biasp[GATES];
__device__ __align__(16) __nv_bfloat16 g_Ah[BATCH * KDIM];
__device__ __align__(16) __nv_bfloat16 g_Al[BATCH * KDIM];
__device__ __align__(16) __nv_bfloat16 g_Wh[(size_t)GATES * KDIM];
__device__ __align__(16) __nv_bfloat16 g_Wl[(size_t)GATES * KDIM];
__device__ __align__(16) __nv_bfloat16 g_Fh[(size_t)HDIM * HDIM];
__device__ __align__(16) __nv_bfloat16 g_Fl[(size_t)HDIM * HDIM];

// ---------------- helpers ----------------
__device__ __forceinline__ uint32_t smem_u32(const void* p) {
    uint32_t a;
    asm("{ .reg .u64 t; cvta.to.shared.u64 t, %1; cvt.u32.u64 %0, t; }" : "=r"(a) : "l"(p));
    return a;
}
static __device__ __forceinline__ void cpa16(uint32_t s, const void* g) {
    asm volatile("cp.async.cg.shared.global [%0], [%1], 16;" :: "r"(s), "l"(g));
}
static __device__ __forceinline__ void cpa_commit() {
    asm volatile("cp.async.commit_group;" ::: "memory");
}
static __device__ __forceinline__ void ldmx4(uint32_t* r, uint32_t addr) {
    asm volatile("ldmatrix.sync.aligned.m8n8.x4.shared.b16 {%0,%1,%2,%3}, [%4];"
                 : "=r"(r[0]), "=r"(r[1]), "=r"(r[2]), "=r"(r[3]) : "r"(addr));
}
static __device__ __forceinline__ void mma16816(float* d, const uint32_t* a, const uint32_t* b) {
    asm volatile(
        "mma.sync.aligned.m16n8k16.row.col.f32.bf16.bf16.f32 "
        "{%0,%1,%2,%3}, {%4,%5,%6,%7}, {%8,%9}, {%0,%1,%2,%3};"
        : "+f"(d[0]), "+f"(d[1]), "+f"(d[2]), "+f"(d[3])
        : "r"(a[0]), "r"(a[1]), "r"(a[2]), "r"(a[3]), "r"(b[0]), "r"(b[1]));
}
static __device__ __forceinline__ float sigm(float v) { return 1.f / (1.f + __expf(-v)); }
static __device__ __forceinline__ float tanhfast(float v) { return 2.f / (1.f + __expf(-2.f * v)) - 1.f; }

// ---------------- init ----------------
__global__ void zero_state() {
    int idx = blockIdx.x * 256 + threadIdx.x;
    g_h[idx] = 0.f;
    g_c[idx] = 0.f;
    int row = idx >> 10, j = idx & 1023;
    __nv_bfloat16 z = __float2bfloat16(0.f);
    g_Ah[(size_t)row * KDIM + 768 + j] = z;
    g_Al[(size_t)row * KDIM + 768 + j] = z;
}

// ---------------- weight convert: (unit,gate) interleave permutation + bf16 split ----------------
__global__ __launch_bounds__(256) void convert_weights(
    const float* __restrict__ W_ih, const float* __restrict__ W_hh,
    const float* __restrict__ b_ih, const float* __restrict__ b_hh)
{
    int pc = blockIdx.x;                    // permuted row: unit = pc>>2, gate = pc&3
    int orig = (pc & 3) * 1024 + (pc >> 2);
    for (int c = threadIdx.x; c < KDIM; c += 256) {
        float w = (c < 768) ? W_ih[(size_t)orig * 768 + c]
                            : W_hh[(size_t)orig * 1024 + (c - 768)];
        __nv_bfloat16 wh = __float2bfloat16(w);
        g_Wh[(size_t)pc * KDIM + c] = wh;
        g_Wl[(size_t)pc * KDIM + c] = __float2bfloat16(w - __bfloat162float(wh));
    }
    if (threadIdx.x == 0) g_biasp[pc] = b_ih[pc & 3 ? orig : orig] + b_hh[orig];
}

__global__ __launch_bounds__(256) void convert_wfc0(const float* __restrict__ W_fc0) {
    int r = blockIdx.x;
    for (int c = threadIdx.x; c < HDIM; c += 256) {
        float w = W_fc0[(size_t)r * HDIM + c];
        __nv_bfloat16 wh = __float2bfloat16(w);
        g_Fh[(size_t)r * HDIM + c] = wh;
        g_Fl[(size_t)r * HDIM + c] = __float2bfloat16(w - __bfloat162float(wh));
    }
}

// ---------------- fused attention + filterbank + glimpse (cp.async channel pipeline) ----------------
__global__ __launch_bounds__(256) void att_glimpse(
    const float* __restrict__ x,
    const float* __restrict__ W_att, const float* __restrict__ b_att)
{
    int b = blockIdx.x;
    int tid = threadIdx.x;

    __shared__ float fx[16][65];
    __shared__ float fy[16][65];
    __shared__ float simg[64][64];
    __shared__ float stmp[16][64];
    __shared__ float red[8][5];
    __shared__ float p[5];
    __shared__ float rs[32];

    // issue ch0 image load via cp.async — overlaps with attention math below
    const float4* img4 = (const float4*)(x + (size_t)b * 3 * 4096);
    float4* simg4 = (float4*)&simg[0][0];
    #pragma unroll
    for (int q = 0; q < 4; q++)
        cpa16(smem_u32(&simg4[tid + q * 256]), &img4[tid + q * 256]);
    cpa_commit();

    // ---- attention params: p = h @ W_att^T + b_att ----
    const float* hrow = g_h + (size_t)b * HDIM;
    float a0 = 0.f, a1 = 0.f, a2 = 0.f, a3 = 0.f, a4 = 0.f;
    for (int k = tid; k < HDIM; k += 256) {
        float hv = hrow[k];
        a0 += hv * W_att[k];
        a1 += hv * W_att[HDIM + k];
        a2 += hv * W_att[2 * HDIM + k];
        a3 += hv * W_att[3 * HDIM + k];
        a4 += hv * W_att[4 * HDIM + k];
    }
    #pragma unroll
    for (int o = 16; o > 0; o >>= 1) {
        a0 += __shfl_down_sync(0xffffffffu, a0, o);
        a1 += __shfl_down_sync(0xffffffffu, a1, o);
        a2 += __shfl_down_sync(0xffffffffu, a2, o);
        a3 += __shfl_down_sync(0xffffffffu, a3, o);
        a4 += __shfl_down_sync(0xffffffffu, a4, o);
    }
    int warp = tid >> 5, lane = tid & 31;
    if (lane == 0) {
        red[warp][0] = a0; red[warp][1] = a1; red[warp][2] = a2;
        red[warp][3] = a3; red[warp][4] = a4;
    }
    __syncthreads();
    if (tid < 5) {
        float s = b_att[tid];
        #pragma unroll
        for (int w = 0; w < 8; w++) s += red[w][tid];
        p[tid] = s;
    }
    __syncthreads();

    float gx     = 32.5f * (p[0] + 1.f);
    float gy     = 32.5f * (p[1] + 1.f);
    float inv2s2 = 0.5f * expf(-p[2]);
    float delta  = (63.f / 15.f) * expf(p[3]);
    float gam    = expf(p[4]);

    // ---- filterbank ----
    for (int idx = tid; idx < 1024; idx += 256) {
        int i = idx >> 6, a = idx & 63;
        float mu = (i - 8.5f) * delta;
        float dx = (float)a - (gx + mu);
        float dy = (float)a - (gy + mu);
        fx[i][a] = __expf(-dx * dx * inv2s2);
        fy[i][a] = __expf(-dy * dy * inv2s2);
    }
    __syncthreads();
    if (tid < 32) {
        float s = 0.f;
        if (tid < 16) {
            for (int a = 0; a < 64; a++) s += fx[tid][a];
        } else {
            for (int a = 0; a < 64; a++) s += fy[tid - 16][a];
        }
        rs[tid] = 1.f / (s + EPSV);
    }
    __syncthreads();
    for (int idx = tid; idx < 1024; idx += 256) {
        int i = idx >> 6, a = idx & 63;
        fx[i][a] *= rs[i];
        fy[i][a] *= rs[16 + i];
    }
    // wait for ch0 image + barrier
    asm volatile("cp.async.wait_group 0;" ::: "memory");
    __syncthreads();

    // ---- glimpse per channel (image loads pipelined over phase2) ----
    for (int c = 0; c < 3; c++) {
        // phase 1: 4 n-outputs per thread
        {
            int a = tid & 63, ng = tid >> 6;
            float ac[4] = {0.f, 0.f, 0.f, 0.f};
            #pragma unroll 8
            for (int y = 0; y < 64; y++) {
                float iv = simg[y][a];
                #pragma unroll
                for (int q = 0; q < 4; q++) ac[q] += fy[ng * 4 + q][y] * iv;
            }
            #pragma unroll
            for (int q = 0; q < 4; q++) stmp[ng * 4 + q][a] = ac[q];
        }
        __syncthreads();

        // prefetch next channel image into simg (nobody reads simg during phase2)
        if (c < 2) {
            const float4* nxt = img4 + (size_t)(c + 1) * 1024;
            #pragma unroll
            for (int q = 0; q < 4; q++)
                cpa16(smem_u32(&simg4[tid + q * 256]), &nxt[tid + q * 256]);
            cpa_commit();
        }

        // phase 2
        int n = tid >> 4, xx = tid & 15;
        float s = 0.f;
        #pragma unroll 8
        for (int a = 0; a < 64; a++) s += stmp[n][a] * fx[xx][a];
        float v = s * gam;
        __nv_bfloat16 vh = __float2bfloat16(v);
        size_t off = (size_t)b * KDIM + c * 256 + tid;
        g_Ah[off] = vh;
        g_Al[off] = __float2bfloat16(v - __bfloat162float(vh));

        asm volatile("cp.async.wait_group 0;" ::: "memory");
        __syncthreads();
    }
}

// ---------------- gates GEMM (mma.sync split-bf16) + fused LSTM epilogue ----------------
// CTA tile 128x256, 256 thr (8 warps, 2x4), warp tile 64x64, BK=32, 3-stage cp.async.
#define TA 10240                 // A tile: 128 rows * 80B
#define TB 20480                 // B tile: 256 rows * 80B
#define STG (2 * TA + 2 * TB)    // 61440
#define NSTG 3
#define GSMEM (NSTG * STG + 1024)
#define NKB 56

__global__ __launch_bounds__(256, 1) void gemm_gates()
{
    extern __shared__ char smem[];
    const int tid = threadIdx.x;
    const int lane = tid & 31;
    const int wid = tid >> 5;
    const int wm = wid >> 2;          // 0..1
    const int wn = wid & 3;           // 0..3
    const int bn = blockIdx.x * 256;
    const int bm = blockIdx.y * 128;
    const int ub = bn >> 2;           // unit base (64 units per CTA)

    float* bias_s = (float*)(smem + NSTG * STG);
    if (tid < 256) bias_s[tid] = g_biasp[bn + tid];

    float acc[4][8][4];
    #pragma unroll
    for (int i = 0; i < 4; i++)
        #pragma unroll
        for (int j = 0; j < 8; j++)
            #pragma unroll
            for (int q = 0; q < 4; q++) acc[i][j][q] = 0.f;

    const uint32_t a_off = (uint32_t)((wm * 64 + (lane & 15)) * 80 + (lane >> 4) * 16);
    const uint32_t b_row = (uint32_t)(wn * 64 + (lane & 7) + ((lane >> 4) << 3));
    const uint32_t b_off = b_row * 80 + (((uint32_t)lane >> 3) & 1) * 16;

    // hoisted per-thread cp.async source pointers (tile selection is static per slot)
    const int rA = tid >> 2;                 // 0..63
    const int chq = (tid & 3) * 8;           // element offset of 16B chunk
    const uint32_t soA = (uint32_t)(rA * 80 + (tid & 3) * 16);
    const __nv_bfloat16* pAh = g_Ah + (size_t)(bm + rA) * KDIM + chq;
    const __nv_bfloat16* pAl = g_Al + (size_t)(bm + rA) * KDIM + chq;
    const __nv_bfloat16* pWh = g_Wh + (size_t)(bn + rA) * KDIM + chq;
    const __nv_bfloat16* pWl = g_Wl + (size_t)(bn + rA) * KDIM + chq;

    auto issue = [&](int kb, char* buf) {
        const int kcol = kb * 32;
        const uint32_t bu = smem_u32(buf);
        // A tiles: rows rA and rA+64
        cpa16(bu + soA,                 pAh + kcol);
        cpa16(bu + soA + 64 * 80,       pAh + kcol + (size_t)64 * KDIM);
        cpa16(bu + TA + soA,            pAl + kcol);
        cpa16(bu + TA + soA + 64 * 80,  pAl + kcol + (size_t)64 * KDIM);
        // B tiles: rows rA, +64, +128, +192
        #pragma unroll
        for (int r = 0; r < 4; r++) {
            cpa16(bu + 2 * TA + soA + r * (64 * 80),      pWh + kcol + (size_t)(r * 64) * KDIM);
            cpa16(bu + 2 * TA + TB + soA + r * (64 * 80), pWl + kcol + (size_t)(r * 64) * KDIM);
        }
    };

    issue(0, smem + 0 * STG);
    cpa_commit();
    issue(1, smem + 1 * STG);
    cpa_commit();

    int s_cur = 0, s_nxt = 2;
    for (int kb = 0; kb < NKB; kb++) {
        if (kb + 2 < NKB) issue(kb + 2, smem + s_nxt * STG);
        cpa_commit();
        asm volatile("cp.async.wait_group 2;" ::: "memory");
        __syncthreads();

        uint32_t sb = smem_u32(smem + s_cur * STG);
        #pragma unroll
        for (int kh = 0; kh < 2; kh++) {
            uint32_t kadd = kh * 32;
            uint32_t aH[4][4], aL[4][4], bH[4][4], bL[4][4];
            #pragma unroll
            for (int mt = 0; mt < 4; mt++)
                ldmx4(aH[mt], sb + a_off + mt * (16 * 80) + kadd);
            #pragma unroll
            for (int g = 0; g < 4; g++)
                ldmx4(bH[g], sb + 2 * TA + b_off + g * (16 * 80) + kadd);

            #pragma unroll
            for (int mt = 0; mt < 4; mt++)
                #pragma unroll
                for (int nt = 0; nt < 8; nt++)
                    mma16816(acc[mt][nt], aH[mt], &bH[nt >> 1][(nt & 1) * 2]);

            #pragma unroll
            for (int g = 0; g < 4; g++)
                ldmx4(bL[g], sb + 2 * TA + TB + b_off + g * (16 * 80) + kadd);
            #pragma unroll
            for (int mt = 0; mt < 4; mt++)
                #pragma unroll
                for (int nt = 0; nt < 8; nt++)
                    mma16816(acc[mt][nt], aH[mt], &bL[nt >> 1][(nt & 1) * 2]);

            #pragma unroll
            for (int mt = 0; mt < 4; mt++)
                ldmx4(aL[mt], sb + TA + a_off + mt * (16 * 80) + kadd);
            #pragma unroll
            for (int mt = 0; mt < 4; mt++)
                #pragma unroll
                for (int nt = 0; nt < 8; nt++)
                    mma16816(acc[mt][nt], aL[mt], &bH[nt >> 1][(nt & 1) * 2]);
        }
        __syncthreads();
        s_cur = (s_cur == 2) ? 0 : s_cur + 1;
        s_nxt = (s_nxt == 2) ? 0 : s_nxt + 1;
    }

    // ---------- fused LSTM epilogue (smem-staged for coalescing) ----------
    float* c_s = (float*)smem;                 // [128][65]
    float* h_s = (float*)(smem + 33536);       // [128][65]

    for (int i = tid; i < 8192; i += 256) {
        int row = i >> 6, u = i & 63;
        c_s[row * 65 + u] = g_c[(size_t)(bm + row) * HDIM + ub + u];
    }
    __syncthreads();

    #pragma unroll
    for (int mt = 0; mt < 4; mt++) {
        #pragma unroll
        for (int nt = 0; nt < 8; nt++) {
            int colbase = wn * 64 + nt * 8 + (lane & 3) * 2;
            float b0 = bias_s[colbase], b1 = bias_s[colbase + 1];
            #pragma unroll
            for (int half = 0; half < 2; half++) {
                float v0 = acc[mt][nt][half * 2 + 0] + b0;
                float v1 = acc[mt][nt][half * 2 + 1] + b1;
                float p0 = __shfl_xor_sync(0xffffffffu, v0, 1);
                float p1 = __shfl_xor_sync(0xffffffffu, v1, 1);
                if (!(lane & 1)) {
                    // v0=i, v1=f, p0=g, p1=o
                    int rowl = wm * 64 + mt * 16 + (lane >> 2) + half * 8;
                    int uc = (colbase >> 2);   // local unit 0..63
                    float ig = sigm(v0);
                    float fg = sigm(v1);
                    float gg = tanhfast(p0);
                    float og = sigm(p1);
                    float cn = fg * c_s[rowl * 65 + uc] + ig * gg;
                    c_s[rowl * 65 + uc] = cn;
                    h_s[rowl * 65 + uc] = og * tanhfast(cn);
                }
            }
        }
    }
    __syncthreads();

    // write out coalesced: c, h, Ah, Al
    for (int i = tid; i < 8192; i += 256) {
        int row = i >> 6, u = i & 63;
        float cn = c_s[row * 65 + u];
        float hn = h_s[row * 65 + u];
        size_t ro = (size_t)(bm + row);
        g_c[ro * HDIM + ub + u] = cn;
        g_h[ro * HDIM + ub + u] = hn;
        __nv_bfloat16 hh = __float2bfloat16(hn);
        g_Ah[ro * KDIM + 768 + ub + u] = hh;
        g_Al[ro * KDIM + 768 + ub + u] = __float2bfloat16(hn - __bfloat162float(hh));
    }
}

// ---------------- fc0 GEMM (mma.sync split-bf16): t = relu(h @ W_fc0^T + b) ----------------
#define FTA 10240
#define FSTG (4 * FTA)           // 40960
#define FSMEM (3 * FSTG + 256)
#define FNKB 32

__global__ __launch_bounds__(256, 1) void gemm_fc0(const float* __restrict__ bias)
{
    extern __shared__ char smem[];
    const int tid = threadIdx.x;
    const int lane = tid & 31;
    const int wid = tid >> 5;
    const int wm = wid >> 2;          // 0..1
    const int wn = wid & 3;           // 0..3
    const int bn = blockIdx.x * 128;
    const int bm = blockIdx.y * 128;

    float acc[4][4][4];
    #pragma unroll
    for (int i = 0; i < 4; i++)
        #pragma unroll
        for (int j = 0; j < 4; j++)
            #pragma unroll
            for (int q = 0; q < 4; q++) acc[i][j][q] = 0.f;

    const uint32_t a_off = (uint32_t)((wm * 64 + (lane & 15)) * 80 + (lane >> 4) * 16);
    const uint32_t b_row = (uint32_t)(wn * 32 + (lane & 7) + ((lane >> 4) << 3));
    const uint32_t b_off = b_row * 80 + (((uint32_t)lane >> 3) & 1) * 16;

    auto issue = [&](int kb, char* buf) {
        int kcol = kb * 32;
        uint32_t bu = smem_u32(buf);
        #pragma unroll
        for (int i = 0; i < 8; i++) {
            int cid = tid + i * 256;
            int t4 = cid >> 9;                // 0=AH 1=AL 2=BH 3=BL
            int w = cid & 511;
            int row = w >> 2, ch = w & 3;
            const __nv_bfloat16* gp;
            if (t4 == 0)      gp = g_Ah + (size_t)(bm + row) * KDIM + 768 + kcol + ch * 8;
            else if (t4 == 1) gp = g_Al + (size_t)(bm + row) * KDIM + 768 + kcol + ch * 8;
            else if (t4 == 2) gp = g_Fh + (size_t)(bn + row) * HDIM + kcol + ch * 8;
            else              gp = g_Fl + (size_t)(bn + row) * HDIM + kcol + ch * 8;
            cpa16(bu + t4 * FTA + row * 80 + ch * 16, gp);
        }
    };

    issue(0, smem + 0 * FSTG);
    cpa_commit();
    issue(1, smem + 1 * FSTG);
    cpa_commit();

    int s_cur = 0, s_nxt = 2;
    for (int kb = 0; kb < FNKB; kb++) {
        if (kb + 2 < FNKB) issue(kb + 2, smem + s_nxt * FSTG);
        cpa_commit();
        asm volatile("cp.async.wait_group 2;" ::: "memory");
        __syncthreads();

        uint32_t sb = smem_u32(smem + s_cur * FSTG);
        #pragma unroll
        for (int kh = 0; kh < 2; kh++) {
            uint32_t kadd = kh * 32;
            uint32_t aH[4][4], aL[4][4], bb[2][4];
            #pragma unroll
            for (int mt = 0; mt < 4; mt++)
                ldmx4(aH[mt], sb + a_off + mt * (16 * 80) + kadd);
            #pragma unroll
            for (int g = 0; g < 2; g++)
                ldmx4(bb[g], sb + 2 * FTA + b_off + g * (16 * 80) + kadd);
            #pragma unroll
            for (int mt = 0; mt < 4; mt++)
                #pragma unroll
                for (int nt = 0; nt < 4; nt++)
                    mma16816(acc[mt][nt], aH[mt], &bb[nt >> 1][(nt & 1) * 2]);
            #pragma unroll
            for (int mt = 0; mt < 4; mt++)
                ldmx4(aL[mt], sb + FTA + a_off + mt * (16 * 80) + kadd);
            #pragma unroll
            for (int mt = 0; mt < 4; mt++)
                #pragma unroll
                for (int nt = 0; nt < 4; nt++)
                    mma16816(acc[mt][nt], aL[mt], &bb[nt >> 1][(nt & 1) * 2]);
            #pragma unroll
            for (int g = 0; g < 2; g++)
                ldmx4(bb[g], sb + 3 * FTA + b_off + g * (16 * 80) + kadd);
            #pragma unroll
            for (int mt = 0; mt < 4; mt++)
                #pragma unroll
                for (int nt = 0; nt < 4; nt++)
                    mma16816(acc[mt][nt], aH[mt], &bb[nt >> 1][(nt & 1) * 2]);
        }
        __syncthreads();
        s_cur = (s_cur == 2) ? 0 : s_cur + 1;
        s_nxt = (s_nxt == 2) ? 0 : s_nxt + 1;
    }

    #pragma unroll
    for (int mt = 0; mt < 4; mt++) {
        int r0 = bm + wm * 64 + mt * 16 + (lane >> 2);
        #pragma unroll
        for (int nt = 0; nt < 4; nt++) {
            int c0 = bn + wn * 32 + nt * 8 + (lane & 3) * 2;
            float b0 = bias[c0], b1 = bias[c0 + 1];
            float v0 = fmaxf(acc[mt][nt][0] + b0, 0.f);
            float v1 = fmaxf(acc[mt][nt][1] + b1, 0.f);
            float v2 = fmaxf(acc[mt][nt][2] + b0, 0.f);
            float v3 = fmaxf(acc[mt][nt][3] + b1, 0.f);
            *(float2*)&g_t[(size_t)r0 * HDIM + c0] = make_float2(v0, v1);
            *(float2*)&g_t[(size_t)(r0 + 8) * HDIM + c0] = make_float2(v2, v3);
        }
    }
}

// ---------------- final small FC ----------------
__global__ __launch_bounds__(256) void fc_out(
    const float* __restrict__ W, const float* __restrict__ bias, float* __restrict__ out)
{
    int b = blockIdx.x;
    int tid = threadIdx.x;
    const float* trow = g_t + (size_t)b * HDIM;
    float acc[10];
    #pragma unroll
    for (int j = 0; j < 10; j++) acc[j] = 0.f;
    for (int k = tid; k < HDIM; k += 256) {
        float tv = trow[k];
        #pragma unroll
        for (int j = 0; j < 10; j++) acc[j] += tv * W[j * HDIM + k];
    }
    #pragma unroll
    for (int j = 0; j < 10; j++)
        #pragma unroll
        for (int o = 16; o > 0; o >>= 1)
            acc[j] += __shfl_down_sync(0xffffffffu, acc[j], o);
    __shared__ float red[8][10];
    int warp = tid >> 5, lane = tid & 31;
    if (lane == 0)
        #pragma unroll
        for (int j = 0; j < 10; j++) red[warp][j] = acc[j];
    __syncthreads();
    if (tid < 10) {
        float s = bias[tid];
        #pragma unroll
        for (int w = 0; w < 8; w++) s += red[w][tid];
        out[b * 10 + tid] = s;
    }
}

// ---------------- launcher ----------------
extern "C" void kernel_launch(void* const* d_in, const int* in_sizes, int n_in,
                              void* d_out, int out_size)
{
    const float* x      = (const float*)d_in[0];
    const float* W_att  = (const float*)d_in[1];
    const float* b_att  = (const float*)d_in[2];
    const float* W_ih   = (const float*)d_in[3];
    const float* W_hh   = (const float*)d_in[4];
    const float* b_ih   = (const float*)d_in[5];
    const float* b_hh   = (const float*)d_in[6];
    const float* W_fc0  = (const float*)d_in[7];
    const float* b_fc0  = (const float*)d_in[8];
    const float* W_fc   = (const float*)d_in[9];
    const float* b_fc   = (const float*)d_in[10];
    float* out = (float*)d_out;

    cudaFuncSetAttribute(gemm_gates, cudaFuncAttributeMaxDynamicSharedMemorySize, GSMEM);
    cudaFuncSetAttribute(gemm_fc0,   cudaFuncAttributeMaxDynamicSharedMemorySize, FSMEM);

    // launch order chosen so ncu (-s 5) profiles gemm_gates:
    // 1 convert_weights, 2 zero_state, 3 att_glimpse, 4 gemm_gates, 5 att_glimpse, 6 gemm_gates <- profiled
    convert_weights<<<GATES, 256>>>(W_ih, W_hh, b_ih, b_hh);
    zero_state<<<(BATCH * HDIM) / 256, 256>>>();

    for (int t = 0; t < 16; t++) {
        att_glimpse<<<BATCH, 256>>>(x, W_att, b_att);
        gemm_gates<<<dim3(GATES / 256, BATCH / 128), 256, GSMEM>>>();
    }

    convert_wfc0<<<HDIM, 256>>>(W_fc0);
    gemm_fc0<<<dim3(HDIM / 128, BATCH / 128), 256, FSMEM>>>(b_fc0);
    fc_out<<<BATCH, 256>>>(W_fc, b_fc, out);
}